// round 15
// baseline (speedup 1.0000x reference)
#include <cuda_runtime.h>
#include <cuda_fp16.h>
#include <mma.h>
#include <math.h>
#include <cstdint>

using namespace nvcuda;

constexpr int S_ = 1024;
constexpr int B_ = 32;
constexpr int E_ = 1024;
constexpr int P_ = 128;
constexpr int NQK = 2 * P_;   // 256

__device__ __half g_qk[(size_t)B_ * S_ * NQK];
__device__ __half g_Wb[(size_t)NQK * E_];
__device__ float g_fwd[B_ * S_];
__device__ float g_bwd[B_ * S_];

__device__ __forceinline__ uint32_t smem_u32(const void* p) {
    uint32_t a;
    asm("{ .reg .u64 t; cvta.to.shared.u64 t, %1; cvt.u32.u64 %0, t; }"
        : "=r"(a) : "l"(p));
    return a;
}
#define CP_ASYNC16(dst_u32, src_ptr) \
    asm volatile("cp.async.cg.shared.global [%0], [%1], 16;" \
                 :: "r"(dst_u32), "l"(src_ptr))
#define CP_COMMIT() asm volatile("cp.async.commit_group;" ::: "memory")
#define CP_WAIT1()  asm volatile("cp.async.wait_group 1;" ::: "memory")

// ---------------------------------------------------------------------------
// Stage 0: convert W (fp32 [256,1024]) to fp16 once.
// ---------------------------------------------------------------------------
__global__ __launch_bounds__(256) void conv_w(const float* __restrict__ W)
{
    int i = blockIdx.x * 256 + threadIdx.x;
    float4 v = ((const float4*)W)[i];
    __half2 p0 = __float22half2_rn(make_float2(v.x, v.y));
    __half2 p1 = __float22half2_rn(make_float2(v.z, v.w));
    *(uint2*)&g_Wb[(size_t)i * 4] = make_uint2(*(unsigned*)&p0, *(unsigned*)&p1);
}

// ---------------------------------------------------------------------------
// Stage 1: GEMM qk = ctx @ W^T. M=32768, N=256, K=1024.
// fp16 wmma m16n16k16 with fp16 accumulators. BM=64, BN=256, BK=16;
// 256 threads (8 warps 2x4). 3 CTAs/SM (reg-capped) for latency coverage.
// ---------------------------------------------------------------------------
constexpr int GBM = 64;
constexpr int GBK = 16;
constexpr int GLD = 24;                 // fp16 per smem row (48B)
constexpr int A_ST = GBM * GLD;
constexpr int B_ST = NQK * GLD;
constexpr int NSLAB = E_ / GBK;         // 64

__global__ __launch_bounds__(256, 3) void gemm_qk(const float* __restrict__ ctx)
{
    __shared__ __half As[2][GBM][GLD];
    __shared__ __half Bs[3][NQK][GLD];

    const int m0 = blockIdx.x * GBM;
    const int tid = threadIdx.x;
    const int warp = tid >> 5;
    const int wr = warp & 1;
    const int wc = warp >> 1;

    const int lr = tid >> 2;          // A row 0..63
    const int lc = (tid & 3) * 4;     // A col start

    const int br0 = tid >> 1;         // B cp.async row base (0..127)
    const int bh0 = tid & 1;
    const uint32_t bs_base = smem_u32(&Bs[0][0][0]);

    wmma::fragment<wmma::accumulator, 16, 16, 16, __half> acc[2][4];
#pragma unroll
    for (int i = 0; i < 2; i++)
#pragma unroll
        for (int j = 0; j < 4; j++)
            wmma::fill_fragment(acc[i][j], __float2half(0.0f));

    auto cpB = [&](int t, int buf) {
#pragma unroll
        for (int it = 0; it < 2; it++) {
            int row = br0 + it * 128;
            const __half* src = g_Wb + (size_t)row * E_ + t * GBK + bh0 * 8;
            uint32_t dst = bs_base + buf * (B_ST * 2) + row * 48 + bh0 * 16;
            CP_ASYNC16(dst, src);
        }
    };

    float4 ra;
    auto ldgA = [&](int t) {
        ra = *(const float4*)(ctx + (size_t)(m0 + lr) * E_ + t * GBK + lc);
    };
    auto stsA = [&](int buf) {
        __half2 a01 = __float22half2_rn(make_float2(ra.x, ra.y));
        __half2 a23 = __float22half2_rn(make_float2(ra.z, ra.w));
        *(uint2*)(uintptr_t)(&As[buf][lr][lc]) =
            make_uint2(*(unsigned*)&a01, *(unsigned*)&a23);
    };

    // prologue
    cpB(0, 0); CP_COMMIT();
    cpB(1, 1); CP_COMMIT();
    ldgA(0);
    stsA(0);
    ldgA(1);
    CP_WAIT1();
    __syncthreads();

    for (int t = 0; t < NSLAB; t++) {
        if (t + 2 < NSLAB) cpB(t + 2, (t + 2) % 3);
        CP_COMMIT();

        const int ab = t & 1;
        const int bb = t % 3;
        wmma::fragment<wmma::matrix_a, 16, 16, 16, __half, wmma::row_major> af[2];
        wmma::fragment<wmma::matrix_b, 16, 16, 16, __half, wmma::col_major> bf[4];
#pragma unroll
        for (int i = 0; i < 2; i++)
            wmma::load_matrix_sync(af[i], &As[ab][wr * 32 + i * 16][0], GLD);
#pragma unroll
        for (int j = 0; j < 4; j++)
            wmma::load_matrix_sync(bf[j], &Bs[bb][wc * 64 + j * 16][0], GLD);
#pragma unroll
        for (int i = 0; i < 2; i++)
#pragma unroll
            for (int j = 0; j < 4; j++)
                wmma::mma_sync(acc[i][j], af[i], bf[j], acc[i][j]);

        if (t + 1 < NSLAB) {
            stsA((t + 1) & 1);
            if (t + 2 < NSLAB) ldgA(t + 2);
            CP_WAIT1();
            __syncthreads();
        }
    }

    // epilogue: direct half store of fragments
#pragma unroll
    for (int i = 0; i < 2; i++)
#pragma unroll
        for (int j = 0; j < 4; j++) {
            __half* dst = g_qk + (size_t)(m0 + wr * 32 + i * 16) * NQK
                               + wc * 64 + j * 16;
            wmma::store_matrix_sync(dst, acc[i][j], NQK, wmma::mem_row_major);
        }
}

// ---------------------------------------------------------------------------
// Stage 2: neighbor scores from fp16 qk, one warp per (s,b).
// ---------------------------------------------------------------------------
__global__ __launch_bounds__(256) void scores(const float* __restrict__ bias)
{
    const int warp = threadIdx.x >> 5;
    const int lane = threadIdx.x & 31;
    const int m = blockIdx.x * 8 + warp;
    const int s = m >> 5;
    const int b = m & 31;
    if (s >= S_ - 1) return;

    const __half* r0 = g_qk + (size_t)m * NQK;
    const __half* r1 = r0 + (size_t)B_ * NQK;

    uint2 uq0 = *(const uint2*)(r0 + lane * 4);
    uint2 uk0 = *(const uint2*)(r0 + P_ + lane * 4);
    uint2 uq1 = *(const uint2*)(r1 + lane * 4);
    uint2 uk1 = *(const uint2*)(r1 + P_ + lane * 4);
    float4 bq = *(const float4*)(bias + lane * 4);
    float4 bk = *(const float4*)(bias + P_ + lane * 4);

    float2 q0a = __half22float2(*(__half2*)&uq0.x);
    float2 q0b = __half22float2(*(__half2*)&uq0.y);
    float2 k0a = __half22float2(*(__half2*)&uk0.x);
    float2 k0b = __half22float2(*(__half2*)&uk0.y);
    float2 q1a = __half22float2(*(__half2*)&uq1.x);
    float2 q1b = __half22float2(*(__half2*)&uq1.y);
    float2 k1a = __half22float2(*(__half2*)&uk1.x);
    float2 k1b = __half22float2(*(__half2*)&uk1.y);

    float tf = (q0a.x + bq.x) * (k1a.x + bk.x)
             + (q0a.y + bq.y) * (k1a.y + bk.y)
             + (q0b.x + bq.z) * (k1b.x + bk.z)
             + (q0b.y + bq.w) * (k1b.y + bk.w);
    float tb = (q1a.x + bq.x) * (k0a.x + bk.x)
             + (q1a.y + bq.y) * (k0a.y + bk.y)
             + (q1b.x + bq.z) * (k0b.x + bk.z)
             + (q1b.y + bq.w) * (k0b.y + bk.w);

#pragma unroll
    for (int o = 16; o > 0; o >>= 1) {
        tf += __shfl_down_sync(0xffffffffu, tf, o);
        tb += __shfl_down_sync(0xffffffffu, tb, o);
    }
    if (lane == 0) {
        g_fwd[b * S_ + s] = tf * (1.0f / (float)E_);
        g_bwd[b * S_ + s] = tb * (1.0f / (float)E_);
    }
}

// ---------------------------------------------------------------------------
// Stage 3+4 fused: per-block softmax/log/scan, then outer product.
// 1024 threads, RPB=64, grid (16,32). Single 8-chain: 1 exp per 8 outputs.
// ---------------------------------------------------------------------------
constexpr int RPB = 64;

__global__ __launch_bounds__(1024, 2) void outerk(
    const float* __restrict__ prior, const int* __restrict__ mask,
    float* __restrict__ out, float* __restrict__ out_na)
{
    const int b  = blockIdx.y;
    const int i0 = blockIdx.x * RPB;
    const int tid = threadIdx.x;
    const int s = tid;

    __shared__ float sc[S_];
    __shared__ float sf[S_];
    __shared__ float s_warp[32];

    const int rm = mask[b * S_ + ((s + 1) & (S_ - 1))];
    float c0v = (s < S_ - 1) ? g_fwd[b * S_ + s] : -INFINITY;
    if (rm == 1) c0v = -INFINITY;
    float c1v = (s > 0) ? g_bwd[b * S_ + s - 1] : -INFINITY;

    float mx = fmaxf(c0v, c1v);
    float e0 = __expf(c0v - mx);
    float e1 = __expf(c1v - mx);
    float inv = 1.0f / (e0 + e1);
    float p0 = e0 * inv;
    float p1 = e1 * inv;

    sc[s] = p1;
    __syncthreads();
    float shift = (s < S_ - 1) ? sc[s + 1] : 0.0f;
    __syncthreads();

    float pv = sqrtf(p0 * shift + 1e-6f);
    float pr = prior[b * S_ + s];
    float na = pr + (1.0f - pr) * pv;
    if (blockIdx.x == 0) out_na[b * S_ + s] = na;

    float lp = logf(na);
    float fv = na;
    if (rm == 1) { lp = 0.0f; fv = 1.0f; }
    sf[s] = fv;

    float v = lp;
    const unsigned lane = s & 31;
#pragma unroll
    for (int o = 1; o < 32; o <<= 1) {
        float n = __shfl_up_sync(0xffffffffu, v, o);
        if (lane >= (unsigned)o) v += n;
    }
    if (lane == 31) s_warp[s >> 5] = v;
    __syncthreads();
    if (s < 32) {
        float w = s_warp[s];
#pragma unroll
        for (int o = 1; o < 32; o <<= 1) {
            float n = __shfl_up_sync(0xffffffffu, w, o);
            if (s >= o) w += n;
        }
        s_warp[s] = w;
    }
    __syncthreads();
    float incl = v + ((s >= 32) ? s_warp[(s >> 5) - 1] : 0.0f);
    sc[s] = incl - lp;
    __syncthreads();

    const int rsub = tid >> 7;            // 0..7 (8 rows in flight)
    const int j0 = (tid & 127) * 8;

    float4 f0 = *(const float4*)&sf[j0];
    float4 f1 = *(const float4*)&sf[j0 + 4];
    float4 c0 = *(const float4*)&sc[j0];
    float4 c1 = *(const float4*)&sc[j0 + 4];

#pragma unroll 4
    for (int sweep = 0; sweep < RPB / 8; sweep++) {
        const int i = i0 + sweep * 8 + rsub;
        const float ci = sc[i];

        float r[8];
        if (j0 + 7 < i) {
            // left of diagonal: 1 exp at right end, multiply leftward
            float v2 = __expf(ci - c1.w);
            r[7] = v2;
            v2 *= f1.z; r[6] = v2;
            v2 *= f1.y; r[5] = v2;
            v2 *= f1.x; r[4] = v2;
            v2 *= f0.w; r[3] = v2;
            v2 *= f0.z; r[2] = v2;
            v2 *= f0.y; r[1] = v2;
            v2 *= f0.x; r[0] = v2;
        } else if (j0 > i) {
            // right of diagonal: 1 exp at left end, multiply rightward
            float v2 = __expf(c0.x - ci);
            r[0] = v2;
            v2 *= f0.x; r[1] = v2;
            v2 *= f0.y; r[2] = v2;
            v2 *= f0.z; r[3] = v2;
            v2 *= f0.w; r[4] = v2;
            v2 *= f1.x; r[5] = v2;
            v2 *= f1.y; r[6] = v2;
            v2 *= f1.z; r[7] = v2;
        } else {
            const float cj[8] = {c0.x, c0.y, c0.z, c0.w, c1.x, c1.y, c1.z, c1.w};
#pragma unroll
            for (int l = 0; l < 8; l++) {
                int j = j0 + l;
                float d = (j > i) ? (cj[l] - ci) : (ci - cj[l]);
                r[l] = (j == i) ? 0.0f : __expf(d);
            }
        }

        float* dst = out + ((size_t)b * S_ + i) * S_ + j0;
        __stcs((float4*)dst,       make_float4(r[0], r[1], r[2], r[3]));
        __stcs((float4*)(dst + 4), make_float4(r[4], r[5], r[6], r[7]));
    }
}

// ---------------------------------------------------------------------------
extern "C" void kernel_launch(void* const* d_in, const int* in_sizes, int n_in,
                              void* d_out, int out_size)
{
    const float* ctx   = (const float*)d_in[0];
    const float* prior = (const float*)d_in[1];
    const int*   mask  = (const int*)d_in[2];
    const float* W     = (const float*)d_in[3];
    const float* bias  = (const float*)d_in[4];

    float* out_c  = (float*)d_out;
    float* out_na = (float*)d_out + (size_t)B_ * S_ * S_;

    conv_w<<<256, 256>>>(W);

    gemm_qk<<<(B_ * S_) / GBM, 256>>>(ctx);

    scores<<<(B_ * S_) / 8, 256>>>(bias);

    dim3 g4(S_ / RPB, B_);
    outerk<<<g4, 1024>>>(prior, mask, out_c, out_na);
}

// round 16
// speedup vs baseline: 1.0391x; 1.0391x over previous
#include <cuda_runtime.h>
#include <cuda_fp16.h>
#include <mma.h>
#include <math.h>
#include <cstdint>

using namespace nvcuda;

constexpr int S_ = 1024;
constexpr int B_ = 32;
constexpr int E_ = 1024;
constexpr int P_ = 128;
constexpr int NQK = 2 * P_;   // 256

__device__ __half g_qk[(size_t)B_ * S_ * NQK];
__device__ __half g_Wb[(size_t)NQK * E_];
__device__ float g_fwd[B_ * S_];
__device__ float g_bwd[B_ * S_];

__device__ __forceinline__ uint32_t smem_u32(const void* p) {
    uint32_t a;
    asm("{ .reg .u64 t; cvta.to.shared.u64 t, %1; cvt.u32.u64 %0, t; }"
        : "=r"(a) : "l"(p));
    return a;
}
#define CP_ASYNC16(dst_u32, src_ptr) \
    asm volatile("cp.async.cg.shared.global [%0], [%1], 16;" \
                 :: "r"(dst_u32), "l"(src_ptr))
#define CP_COMMIT() asm volatile("cp.async.commit_group;" ::: "memory")
#define CP_WAIT2()  asm volatile("cp.async.wait_group 2;" ::: "memory")

// ---------------------------------------------------------------------------
// Stage 0: convert W (fp32 [256,1024]) to fp16 once.
// ---------------------------------------------------------------------------
__global__ __launch_bounds__(256) void conv_w(const float* __restrict__ W)
{
    int i = blockIdx.x * 256 + threadIdx.x;
    float4 v = ((const float4*)W)[i];
    __half2 p0 = __float22half2_rn(make_float2(v.x, v.y));
    __half2 p1 = __float22half2_rn(make_float2(v.z, v.w));
    *(uint2*)&g_Wb[(size_t)i * 4] = make_uint2(*(unsigned*)&p0, *(unsigned*)&p1);
}

// ---------------------------------------------------------------------------
// Stage 1: GEMM qk = ctx @ W^T. M=32768, N=256, K=1024.
// fp16 wmma m16n16k16, fp16 accumulators. BM=64, BN=256, BK=16; 256 threads.
// A: 3-stage smem + 2-entry reg ring (2 slabs of LDG coverage).
// B: 4-stage cp.async ring, wait_group 2 (2 slabs of coverage).
// ---------------------------------------------------------------------------
constexpr int GBM = 64;
constexpr int GBK = 16;
constexpr int GLD = 24;                 // fp16 per smem row (48B)
constexpr int A_ST = GBM * GLD;
constexpr int B_ST = NQK * GLD;
constexpr int NSLAB = E_ / GBK;         // 64

__global__ __launch_bounds__(256, 2) void gemm_qk(const float* __restrict__ ctx)
{
    __shared__ __half As[3][GBM][GLD];
    __shared__ __half Bs[4][NQK][GLD];

    const int m0 = blockIdx.x * GBM;
    const int tid = threadIdx.x;
    const int warp = tid >> 5;
    const int wr = warp & 1;
    const int wc = warp >> 1;

    const int lr = tid >> 2;          // A row 0..63
    const int lc = (tid & 3) * 4;     // A col start

    const int br0 = tid >> 1;         // B cp.async row base (0..127)
    const int bh0 = tid & 1;
    const uint32_t bs_base = smem_u32(&Bs[0][0][0]);

    wmma::fragment<wmma::accumulator, 16, 16, 16, __half> acc[2][4];
#pragma unroll
    for (int i = 0; i < 2; i++)
#pragma unroll
        for (int j = 0; j < 4; j++)
            wmma::fill_fragment(acc[i][j], __float2half(0.0f));

    auto cpB = [&](int t, int buf) {
#pragma unroll
        for (int it = 0; it < 2; it++) {
            int row = br0 + it * 128;
            const __half* src = g_Wb + (size_t)row * E_ + t * GBK + bh0 * 8;
            uint32_t dst = bs_base + buf * (B_ST * 2) + row * 48 + bh0 * 16;
            CP_ASYNC16(dst, src);
        }
    };

    float4 ra[2];
    auto ldgA = [&](int t) {
        ra[t & 1] = *(const float4*)(ctx + (size_t)(m0 + lr) * E_ + t * GBK + lc);
    };
    auto stsA = [&](int t) {
        const float4& r = ra[t & 1];
        __half2 a01 = __float22half2_rn(make_float2(r.x, r.y));
        __half2 a23 = __float22half2_rn(make_float2(r.z, r.w));
        *(uint2*)(uintptr_t)(&As[t % 3][lr][lc]) =
            make_uint2(*(unsigned*)&a01, *(unsigned*)&a23);
    };

    // prologue
    cpB(0, 0); CP_COMMIT();
    cpB(1, 1); CP_COMMIT();
    cpB(2, 2); CP_COMMIT();
    ldgA(0);
    stsA(0);              // frees ra[0]
    ldgA(1);              // ra[1]
    ldgA(2);              // ra[0]
    CP_WAIT2();           // B(0) landed
    __syncthreads();

    for (int t = 0; t < NSLAB; t++) {
        if (t + 3 < NSLAB) cpB(t + 3, (t + 3) & 3);
        CP_COMMIT();       // uniform wait depth

        const int ab = t % 3;
        const int bb = t & 3;
        wmma::fragment<wmma::matrix_a, 16, 16, 16, __half, wmma::row_major> af[2];
        wmma::fragment<wmma::matrix_b, 16, 16, 16, __half, wmma::col_major> bf[4];
#pragma unroll
        for (int i = 0; i < 2; i++)
            wmma::load_matrix_sync(af[i], &As[ab][wr * 32 + i * 16][0], GLD);
#pragma unroll
        for (int j = 0; j < 4; j++)
            wmma::load_matrix_sync(bf[j], &Bs[bb][wc * 64 + j * 16][0], GLD);
#pragma unroll
        for (int i = 0; i < 2; i++)
#pragma unroll
            for (int j = 0; j < 4; j++)
                wmma::mma_sync(acc[i][j], af[i], bf[j], acc[i][j]);

        if (t + 1 < NSLAB) {
            stsA(t + 1);                       // consumes ra[(t+1)&1]
            if (t + 3 < NSLAB) ldgA(t + 3);    // refills the freed slot
            CP_WAIT2();                        // B(t+1) landed
            __syncthreads();
        }
    }

    // epilogue: direct half store of fragments
#pragma unroll
    for (int i = 0; i < 2; i++)
#pragma unroll
        for (int j = 0; j < 4; j++) {
            __half* dst = g_qk + (size_t)(m0 + wr * 32 + i * 16) * NQK
                               + wc * 64 + j * 16;
            wmma::store_matrix_sync(dst, acc[i][j], NQK, wmma::mem_row_major);
        }
}

// ---------------------------------------------------------------------------
// Stage 2: neighbor scores from fp16 qk, one warp per (s,b).
// ---------------------------------------------------------------------------
__global__ __launch_bounds__(256) void scores(const float* __restrict__ bias)
{
    const int warp = threadIdx.x >> 5;
    const int lane = threadIdx.x & 31;
    const int m = blockIdx.x * 8 + warp;
    const int s = m >> 5;
    const int b = m & 31;
    if (s >= S_ - 1) return;

    const __half* r0 = g_qk + (size_t)m * NQK;
    const __half* r1 = r0 + (size_t)B_ * NQK;

    uint2 uq0 = *(const uint2*)(r0 + lane * 4);
    uint2 uk0 = *(const uint2*)(r0 + P_ + lane * 4);
    uint2 uq1 = *(const uint2*)(r1 + lane * 4);
    uint2 uk1 = *(const uint2*)(r1 + P_ + lane * 4);
    float4 bq = *(const float4*)(bias + lane * 4);
    float4 bk = *(const float4*)(bias + P_ + lane * 4);

    float2 q0a = __half22float2(*(__half2*)&uq0.x);
    float2 q0b = __half22float2(*(__half2*)&uq0.y);
    float2 k0a = __half22float2(*(__half2*)&uk0.x);
    float2 k0b = __half22float2(*(__half2*)&uk0.y);
    float2 q1a = __half22float2(*(__half2*)&uq1.x);
    float2 q1b = __half22float2(*(__half2*)&uq1.y);
    float2 k1a = __half22float2(*(__half2*)&uk1.x);
    float2 k1b = __half22float2(*(__half2*)&uk1.y);

    float tf = (q0a.x + bq.x) * (k1a.x + bk.x)
             + (q0a.y + bq.y) * (k1a.y + bk.y)
             + (q0b.x + bq.z) * (k1b.x + bk.z)
             + (q0b.y + bq.w) * (k1b.y + bk.w);
    float tb = (q1a.x + bq.x) * (k0a.x + bk.x)
             + (q1a.y + bq.y) * (k0a.y + bk.y)
             + (q1b.x + bq.z) * (k0b.x + bk.z)
             + (q1b.y + bq.w) * (k0b.y + bk.w);

#pragma unroll
    for (int o = 16; o > 0; o >>= 1) {
        tf += __shfl_down_sync(0xffffffffu, tf, o);
        tb += __shfl_down_sync(0xffffffffu, tb, o);
    }
    if (lane == 0) {
        g_fwd[b * S_ + s] = tf * (1.0f / (float)E_);
        g_bwd[b * S_ + s] = tb * (1.0f / (float)E_);
    }
}

// ---------------------------------------------------------------------------
// Stage 3+4 fused: per-block softmax/log/scan, then outer product.
// 1024 threads, RPB=64, grid (16,32). Dual 4-chains (round-14 config).
// ---------------------------------------------------------------------------
constexpr int RPB = 64;

__global__ __launch_bounds__(1024, 2) void outerk(
    const float* __restrict__ prior, const int* __restrict__ mask,
    float* __restrict__ out, float* __restrict__ out_na)
{
    const int b  = blockIdx.y;
    const int i0 = blockIdx.x * RPB;
    const int tid = threadIdx.x;
    const int s = tid;

    __shared__ float sc[S_];
    __shared__ float sf[S_];
    __shared__ float s_warp[32];

    const int rm = mask[b * S_ + ((s + 1) & (S_ - 1))];
    float c0v = (s < S_ - 1) ? g_fwd[b * S_ + s] : -INFINITY;
    if (rm == 1) c0v = -INFINITY;
    float c1v = (s > 0) ? g_bwd[b * S_ + s - 1] : -INFINITY;

    float mx = fmaxf(c0v, c1v);
    float e0 = __expf(c0v - mx);
    float e1 = __expf(c1v - mx);
    float inv = 1.0f / (e0 + e1);
    float p0 = e0 * inv;
    float p1 = e1 * inv;

    sc[s] = p1;
    __syncthreads();
    float shift = (s < S_ - 1) ? sc[s + 1] : 0.0f;
    __syncthreads();

    float pv = sqrtf(p0 * shift + 1e-6f);
    float pr = prior[b * S_ + s];
    float na = pr + (1.0f - pr) * pv;
    if (blockIdx.x == 0) out_na[b * S_ + s] = na;

    float lp = logf(na);
    float fv = na;
    if (rm == 1) { lp = 0.0f; fv = 1.0f; }
    sf[s] = fv;

    float v = lp;
    const unsigned lane = s & 31;
#pragma unroll
    for (int o = 1; o < 32; o <<= 1) {
        float n = __shfl_up_sync(0xffffffffu, v, o);
        if (lane >= (unsigned)o) v += n;
    }
    if (lane == 31) s_warp[s >> 5] = v;
    __syncthreads();
    if (s < 32) {
        float w = s_warp[s];
#pragma unroll
        for (int o = 1; o < 32; o <<= 1) {
            float n = __shfl_up_sync(0xffffffffu, w, o);
            if (s >= o) w += n;
        }
        s_warp[s] = w;
    }
    __syncthreads();
    float incl = v + ((s >= 32) ? s_warp[(s >> 5) - 1] : 0.0f);
    sc[s] = incl - lp;
    __syncthreads();

    const int rsub = tid >> 7;            // 0..7 (8 rows in flight)
    const int j0 = (tid & 127) * 8;

    float4 f0 = *(const float4*)&sf[j0];
    float4 f1 = *(const float4*)&sf[j0 + 4];
    float4 c0 = *(const float4*)&sc[j0];
    float4 c1 = *(const float4*)&sc[j0 + 4];

#pragma unroll 4
    for (int sweep = 0; sweep < RPB / 8; sweep++) {
        const int i = i0 + sweep * 8 + rsub;
        const float ci = sc[i];

        float r[8];
        if (j0 + 7 < i) {
            float v2 = __expf(ci - c0.w);
            r[3] = v2;
            v2 *= f0.z; r[2] = v2;
            v2 *= f0.y; r[1] = v2;
            v2 *= f0.x; r[0] = v2;
            float w2 = __expf(ci - c1.w);
            r[7] = w2;
            w2 *= f1.z; r[6] = w2;
            w2 *= f1.y; r[5] = w2;
            w2 *= f1.x; r[4] = w2;
        } else if (j0 > i) {
            float v2 = __expf(c0.x - ci);
            r[0] = v2;
            v2 *= f0.x; r[1] = v2;
            v2 *= f0.y; r[2] = v2;
            v2 *= f0.z; r[3] = v2;
            float w2 = __expf(c1.x - ci);
            r[4] = w2;
            w2 *= f1.x; r[5] = w2;
            w2 *= f1.y; r[6] = w2;
            w2 *= f1.z; r[7] = w2;
        } else {
            const float cj[8] = {c0.x, c0.y, c0.z, c0.w, c1.x, c1.y, c1.z, c1.w};
#pragma unroll
            for (int l = 0; l < 8; l++) {
                int j = j0 + l;
                float d = (j > i) ? (cj[l] - ci) : (ci - cj[l]);
                r[l] = (j == i) ? 0.0f : __expf(d);
            }
        }

        float* dst = out + ((size_t)b * S_ + i) * S_ + j0;
        __stcs((float4*)dst,       make_float4(r[0], r[1], r[2], r[3]));
        __stcs((float4*)(dst + 4), make_float4(r[4], r[5], r[6], r[7]));
    }
}

// ---------------------------------------------------------------------------
extern "C" void kernel_launch(void* const* d_in, const int* in_sizes, int n_in,
                              void* d_out, int out_size)
{
    const float* ctx   = (const float*)d_in[0];
    const float* prior = (const float*)d_in[1];
    const int*   mask  = (const int*)d_in[2];
    const float* W     = (const float*)d_in[3];
    const float* bias  = (const float*)d_in[4];

    float* out_c  = (float*)d_out;
    float* out_na = (float*)d_out + (size_t)B_ * S_ * S_;

    conv_w<<<256, 256>>>(W);

    gemm_qk<<<(B_ * S_) / GBM, 256>>>(ctx);

    scores<<<(B_ * S_) / 8, 256>>>(bias);

    dim3 g4(S_ / RPB, B_);
    outerk<<<g4, 1024>>>(prior, mask, out_c, out_na);
}